// round 5
// baseline (speedup 1.0000x reference)
#include <cuda_runtime.h>
#include <cuda_bf16.h>
#include <math.h>

#define N_NODES 50000
#define IN_DIM  256
#define OUT_DIM 128
#define HEADS   2
#define F_OUT   256
#define N_EDGES 800000

/* ---------------- scratch ---------------- */
__device__ float g_Wh[(size_t)N_NODES * F_OUT];
__device__ float g_s[N_NODES * HEADS];
__device__ float g_t[N_NODES * HEADS];
__device__ int   g_deg[N_NODES];
__device__ int   g_row[N_NODES + 1];
__device__ int   g_cursor[N_NODES];
__device__ int   g_csr_dst[N_EDGES];
__device__ int   g_esrc[N_EDGES];
__device__ int   g_edst[N_EDGES];
__device__ int   g_is64;

/* ---------------- 0: detect int32 vs int64 ---------------- */
__global__ void detect_kernel(const int* ei) {
    int v = ei[2 * threadIdx.x + 1];
    int any = __syncthreads_or(v != 0);
    if (threadIdx.x == 0) g_is64 = !any;
}

/* ---------------- 1: init ---------------- */
__global__ void init_kernel() {
    int i = blockIdx.x * blockDim.x + threadIdx.x;
    if (i < N_NODES) g_deg[i] = 0;
    if (i < N_NODES * HEADS) { g_s[i] = 0.0f; g_t[i] = 0.0f; }
}

/* ---------------- 2: 3xBF16 split-GEMM (BM=128, BN=128), fused s/t ------ */
__device__ __forceinline__ void mma_bf16(float c[4], unsigned a0, unsigned a1,
                                         unsigned a2, unsigned a3,
                                         unsigned b0, unsigned b1) {
    asm volatile(
        "mma.sync.aligned.m16n8k16.row.col.f32.bf16.bf16.f32 "
        "{%0,%1,%2,%3},{%4,%5,%6,%7},{%8,%9},{%0,%1,%2,%3};"
        : "+f"(c[0]), "+f"(c[1]), "+f"(c[2]), "+f"(c[3])
        : "r"(a0), "r"(a1), "r"(a2), "r"(a3), "r"(b0), "r"(b1));
}

__device__ __forceinline__ void split2(float x, float y, unsigned& hi, unsigned& lo) {
    __nv_bfloat162 h = __floats2bfloat162_rn(x, y);
    float rx = x - __bfloat162float(h.x);
    float ry = y - __bfloat162float(h.y);
    __nv_bfloat162 l = __floats2bfloat162_rn(rx, ry);
    hi = *(unsigned*)&h;
    lo = *(unsigned*)&l;
}

__global__ void __launch_bounds__(256) gemm_kernel(const float* __restrict__ A,
                                                   const float* __restrict__ W,
                                                   const float* __restrict__ bias,
                                                   const float* __restrict__ a_vec) {
    /* pair-packed bf16x2 tiles: index [kp][row/n], k = 2*kp, 2*kp+1 */
    __shared__ unsigned Ah[16][136];
    __shared__ unsigned Al[16][136];
    __shared__ unsigned Bh[16][136];
    __shared__ unsigned Bl[16][136];

    const int bm = blockIdx.y * 128;
    const int bn = blockIdx.x * 128;   /* 0 or 128 -> head */
    const int tid  = threadIdx.x;
    const int lane = tid & 31;
    const int wid  = tid >> 5;
    const int warp_m = wid >> 1;       /* 0..3, 32 rows each */
    const int warp_n = wid & 1;        /* 0..1, 64 cols each */
    const int g  = lane >> 2;
    const int tc = lane & 3;
    const int head = (bn >= 128) ? 1 : 0;

    float c[2][8][4];
    #pragma unroll
    for (int mi = 0; mi < 2; mi++)
        #pragma unroll
        for (int ni = 0; ni < 8; ni++)
            #pragma unroll
            for (int r = 0; r < 4; r++) c[mi][ni][r] = 0.0f;

    for (int k0 = 0; k0 < IN_DIM; k0 += 32) {
        /* --- A tile 128 rows x 32 k --- */
        #pragma unroll
        for (int p = 0; p < 4; p++) {
            int row = p * 32 + (tid >> 3);
            int kq  = (tid & 7) * 4;
            int kp  = kq >> 1;
            int gr  = bm + row;
            float4 v = make_float4(0.f, 0.f, 0.f, 0.f);
            if (gr < N_NODES)
                v = *(const float4*)&A[(size_t)gr * IN_DIM + k0 + kq];
            unsigned h0, l0, h1, l1;
            split2(v.x, v.y, h0, l0);
            split2(v.z, v.w, h1, l1);
            Ah[kp][row]     = h0;  Al[kp][row]     = l0;
            Ah[kp + 1][row] = h1;  Al[kp + 1][row] = l1;
        }
        /* --- B tile 32 k x 128 n --- */
        #pragma unroll
        for (int p = 0; p < 2; p++) {
            int id = tid + p * 256;          /* 0..511 */
            int kp = id >> 5;                /* 0..15 */
            int n4 = (id & 31) * 4;
            const float* w0 = &W[(size_t)(k0 + 2 * kp) * F_OUT + bn + n4];
            float4 v0 = *(const float4*)w0;
            float4 v1 = *(const float4*)(w0 + F_OUT);
            unsigned h, l;
            split2(v0.x, v1.x, h, l); Bh[kp][n4 + 0] = h; Bl[kp][n4 + 0] = l;
            split2(v0.y, v1.y, h, l); Bh[kp][n4 + 1] = h; Bl[kp][n4 + 1] = l;
            split2(v0.z, v1.z, h, l); Bh[kp][n4 + 2] = h; Bl[kp][n4 + 2] = l;
            split2(v0.w, v1.w, h, l); Bh[kp][n4 + 3] = h; Bl[kp][n4 + 3] = l;
        }
        __syncthreads();

        #pragma unroll
        for (int kk = 0; kk < 2; kk++) {
            unsigned ah[2][4], al[2][4], bh[8][2], bl[8][2];
            #pragma unroll
            for (int mi = 0; mi < 2; mi++) {
                int rb = warp_m * 32 + mi * 16;
                int kp = kk * 8 + tc;
                ah[mi][0] = Ah[kp][rb + g];         al[mi][0] = Al[kp][rb + g];
                ah[mi][1] = Ah[kp][rb + g + 8];     al[mi][1] = Al[kp][rb + g + 8];
                ah[mi][2] = Ah[kp + 4][rb + g];     al[mi][2] = Al[kp + 4][rb + g];
                ah[mi][3] = Ah[kp + 4][rb + g + 8]; al[mi][3] = Al[kp + 4][rb + g + 8];
            }
            #pragma unroll
            for (int ni = 0; ni < 8; ni++) {
                int n = warp_n * 64 + ni * 8 + g;
                int kp = kk * 8 + tc;
                bh[ni][0] = Bh[kp][n];     bl[ni][0] = Bl[kp][n];
                bh[ni][1] = Bh[kp + 4][n]; bl[ni][1] = Bl[kp + 4][n];
            }
            #pragma unroll
            for (int mi = 0; mi < 2; mi++)
                #pragma unroll
                for (int ni = 0; ni < 8; ni++) {
                    mma_bf16(c[mi][ni], ah[mi][0], ah[mi][1], ah[mi][2], ah[mi][3],
                             bl[ni][0], bl[ni][1]);
                    mma_bf16(c[mi][ni], al[mi][0], al[mi][1], al[mi][2], al[mi][3],
                             bh[ni][0], bh[ni][1]);
                    mma_bf16(c[mi][ni], ah[mi][0], ah[mi][1], ah[mi][2], ah[mi][3],
                             bh[ni][0], bh[ni][1]);
                }
        }
        __syncthreads();
    }

    /* epilogue: store Wh + partial s,t dots */
    #pragma unroll
    for (int mi = 0; mi < 2; mi++) {
        int r0 = bm + warp_m * 32 + mi * 16 + g;
        int r1 = r0 + 8;
        float ps0 = 0.f, pt0 = 0.f, ps1 = 0.f, pt1 = 0.f;
        #pragma unroll
        for (int ni = 0; ni < 8; ni++) {
            int cb = bn + warp_n * 64 + ni * 8 + tc * 2;
            int dloc = cb - head * OUT_DIM;
            float b0 = bias[cb], b1 = bias[cb + 1];
            float as0 = a_vec[dloc],           as1 = a_vec[dloc + 1];
            float ad0 = a_vec[OUT_DIM + dloc], ad1 = a_vec[OUT_DIM + dloc + 1];
            float v00 = c[mi][ni][0] + b0, v01 = c[mi][ni][1] + b1;
            float v10 = c[mi][ni][2] + b0, v11 = c[mi][ni][3] + b1;
            if (r0 < N_NODES) {
                g_Wh[(size_t)r0 * F_OUT + cb]     = v00;
                g_Wh[(size_t)r0 * F_OUT + cb + 1] = v01;
            }
            if (r1 < N_NODES) {
                g_Wh[(size_t)r1 * F_OUT + cb]     = v10;
                g_Wh[(size_t)r1 * F_OUT + cb + 1] = v11;
            }
            ps0 = fmaf(v00, as0, fmaf(v01, as1, ps0));
            pt0 = fmaf(v00, ad0, fmaf(v01, ad1, pt0));
            ps1 = fmaf(v10, as0, fmaf(v11, as1, ps1));
            pt1 = fmaf(v10, ad0, fmaf(v11, ad1, pt1));
        }
        #pragma unroll
        for (int o = 2; o > 0; o >>= 1) {
            ps0 += __shfl_down_sync(0xffffffffu, ps0, o);
            pt0 += __shfl_down_sync(0xffffffffu, pt0, o);
            ps1 += __shfl_down_sync(0xffffffffu, ps1, o);
            pt1 += __shfl_down_sync(0xffffffffu, pt1, o);
        }
        if (tc == 0) {
            if (r0 < N_NODES) {
                atomicAdd(&g_s[2 * r0 + head], ps0);
                atomicAdd(&g_t[2 * r0 + head], pt0);
            }
            if (r1 < N_NODES) {
                atomicAdd(&g_s[2 * r1 + head], ps1);
                atomicAdd(&g_t[2 * r1 + head], pt1);
            }
        }
    }
}

/* ---------------- 3: degree histogram + edge decode ---------------- */
__global__ void deg_kernel(const int* __restrict__ ei) {
    int i = blockIdx.x * blockDim.x + threadIdx.x;
    if (i >= N_EDGES) return;
    int src, dst;
    if (g_is64) { src = ei[2 * i]; dst = ei[2 * (N_EDGES + i)]; }
    else        { src = ei[i];     dst = ei[N_EDGES + i]; }
    g_esrc[i] = src;
    g_edst[i] = dst;
    atomicAdd(&g_deg[src], 1);
}

/* ---------------- 4: single-block exclusive scan (8 items/thread) ---- */
__global__ void scan_kernel() {
    const int tid = threadIdx.x, lane = tid & 31, wid = tid >> 5;
    __shared__ int wsum[32];
    __shared__ int s_carry;
    if (tid == 0) s_carry = 0;
    __syncthreads();
    for (int base = 0; base < N_NODES; base += 8192) {
        int i0 = base + tid * 8;
        int v[8], pref[8];
        int run = 0;
        #pragma unroll
        for (int j = 0; j < 8; j++) {
            v[j] = (i0 + j < N_NODES) ? g_deg[i0 + j] : 0;
            pref[j] = run;
            run += v[j];
        }
        int x = run;
        #pragma unroll
        for (int o = 1; o < 32; o <<= 1) {
            int y = __shfl_up_sync(0xffffffffu, x, o);
            if (lane >= o) x += y;
        }
        if (lane == 31) wsum[wid] = x;
        __syncthreads();
        if (wid == 0) {
            int w = wsum[lane];
            #pragma unroll
            for (int o = 1; o < 32; o <<= 1) {
                int y = __shfl_up_sync(0xffffffffu, w, o);
                if (lane >= o) w += y;
            }
            wsum[lane] = w;
        }
        __syncthreads();
        int off = s_carry + ((wid == 0) ? 0 : wsum[wid - 1]) + (x - run);
        #pragma unroll
        for (int j = 0; j < 8; j++) {
            int i = i0 + j;
            if (i < N_NODES) { g_row[i] = off + pref[j]; g_cursor[i] = off + pref[j]; }
        }
        __syncthreads();
        if (tid == 0) s_carry += wsum[31];
        __syncthreads();
    }
    if (tid == 0) g_row[N_NODES] = s_carry;
}

/* ---------------- 5: scatter into CSR ---------------- */
__global__ void scatter_kernel() {
    int i = blockIdx.x * blockDim.x + threadIdx.x;
    if (i >= N_EDGES) return;
    int src = g_esrc[i];
    int p = atomicAdd(&g_cursor[src], 1);
    g_csr_dst[p] = g_edst[i];
}

/* ---------------- 6: fused softmax+agg (warp per node, unroll 4) ------ */
__global__ void __launch_bounds__(256) agg_kernel(float* __restrict__ out) {
    int n = (blockIdx.x * blockDim.x + threadIdx.x) >> 5;
    int lane = threadIdx.x & 31;
    if (n >= N_NODES) return;
    int start = g_row[n], end = g_row[n + 1];
    float* o = out + (size_t)n * F_OUT + lane * 8;
    const float* whn = g_Wh + (size_t)n * F_OUT + lane * 8;

    if (start == end) {
        *(float4*)o       = *(const float4*)whn;
        *(float4*)(o + 4) = *(const float4*)(whn + 4);
        return;
    }

    int head = lane >> 4;
    float s_h = g_s[2 * n + head];
    float4 acc0 = make_float4(0.f, 0.f, 0.f, 0.f);
    float4 acc1 = make_float4(0.f, 0.f, 0.f, 0.f);
    float den = 0.0f;

    int i = start;
    for (; i + 3 < end; i += 4) {
        int d0 = g_csr_dst[i];
        int d1 = g_csr_dst[i + 1];
        int d2 = g_csr_dst[i + 2];
        int d3 = g_csr_dst[i + 3];
        float t0 = g_t[2 * d0 + head];
        float t1 = g_t[2 * d1 + head];
        float t2 = g_t[2 * d2 + head];
        float t3 = g_t[2 * d3 + head];
        const float4* w0 = (const float4*)(g_Wh + (size_t)d0 * F_OUT + lane * 8);
        const float4* w1 = (const float4*)(g_Wh + (size_t)d1 * F_OUT + lane * 8);
        const float4* w2 = (const float4*)(g_Wh + (size_t)d2 * F_OUT + lane * 8);
        const float4* w3 = (const float4*)(g_Wh + (size_t)d3 * F_OUT + lane * 8);
        float4 v00 = w0[0], v01 = w0[1];
        float4 v10 = w1[0], v11 = w1[1];
        float4 v20 = w2[0], v21 = w2[1];
        float4 v30 = w3[0], v31 = w3[1];
        float e0 = s_h + t0; e0 = e0 > 0.f ? e0 : 0.2f * e0;
        float e1 = s_h + t1; e1 = e1 > 0.f ? e1 : 0.2f * e1;
        float e2 = s_h + t2; e2 = e2 > 0.f ? e2 : 0.2f * e2;
        float e3 = s_h + t3; e3 = e3 > 0.f ? e3 : 0.2f * e3;
        float ex0 = expf(e0), ex1 = expf(e1), ex2 = expf(e2), ex3 = expf(e3);
        den += (ex0 + ex1) + (ex2 + ex3);
        acc0.x = fmaf(ex0, v00.x, acc0.x); acc0.y = fmaf(ex0, v00.y, acc0.y);
        acc0.z = fmaf(ex0, v00.z, acc0.z); acc0.w = fmaf(ex0, v00.w, acc0.w);
        acc1.x = fmaf(ex0, v01.x, acc1.x); acc1.y = fmaf(ex0, v01.y, acc1.y);
        acc1.z = fmaf(ex0, v01.z, acc1.z); acc1.w = fmaf(ex0, v01.w, acc1.w);
        acc0.x = fmaf(ex1, v10.x, acc0.x); acc0.y = fmaf(ex1, v10.y, acc0.y);
        acc0.z = fmaf(ex1, v10.z, acc0.z); acc0.w = fmaf(ex1, v10.w, acc0.w);
        acc1.x = fmaf(ex1, v11.x, acc1.x); acc1.y = fmaf(ex1, v11.y, acc1.y);
        acc1.z = fmaf(ex1, v11.z, acc1.z); acc1.w = fmaf(ex1, v11.w, acc1.w);
        acc0.x = fmaf(ex2, v20.x, acc0.x); acc0.y = fmaf(ex2, v20.y, acc0.y);
        acc0.z = fmaf(ex2, v20.z, acc0.z); acc0.w = fmaf(ex2, v20.w, acc0.w);
        acc1.x = fmaf(ex2, v21.x, acc1.x); acc1.y = fmaf(ex2, v21.y, acc1.y);
        acc1.z = fmaf(ex2, v21.z, acc1.z); acc1.w = fmaf(ex2, v21.w, acc1.w);
        acc0.x = fmaf(ex3, v30.x, acc0.x); acc0.y = fmaf(ex3, v30.y, acc0.y);
        acc0.z = fmaf(ex3, v30.z, acc0.z); acc0.w = fmaf(ex3, v30.w, acc0.w);
        acc1.x = fmaf(ex3, v31.x, acc1.x); acc1.y = fmaf(ex3, v31.y, acc1.y);
        acc1.z = fmaf(ex3, v31.z, acc1.z); acc1.w = fmaf(ex3, v31.w, acc1.w);
    }
    for (; i < end; i++) {
        int d = g_csr_dst[i];
        float t = g_t[2 * d + head];
        const float4* w = (const float4*)(g_Wh + (size_t)d * F_OUT + lane * 8);
        float4 v0 = w[0], v1 = w[1];
        float e = s_h + t; e = e > 0.f ? e : 0.2f * e;
        float ex = expf(e);
        den += ex;
        acc0.x = fmaf(ex, v0.x, acc0.x); acc0.y = fmaf(ex, v0.y, acc0.y);
        acc0.z = fmaf(ex, v0.z, acc0.z); acc0.w = fmaf(ex, v0.w, acc0.w);
        acc1.x = fmaf(ex, v1.x, acc1.x); acc1.y = fmaf(ex, v1.y, acc1.y);
        acc1.z = fmaf(ex, v1.z, acc1.z); acc1.w = fmaf(ex, v1.w, acc1.w);
    }
    float inv = 1.0f / den;
    acc0.x *= inv; acc0.y *= inv; acc0.z *= inv; acc0.w *= inv;
    acc1.x *= inv; acc1.y *= inv; acc1.z *= inv; acc1.w *= inv;
    *(float4*)o       = acc0;
    *(float4*)(o + 4) = acc1;
}

/* ---------------- launch ---------------- */
extern "C" void kernel_launch(void* const* d_in, const int* in_sizes, int n_in,
                              void* d_out, int out_size) {
    const float* x  = (const float*)d_in[0];
    const int*   ei = (const int*)d_in[1];
    const float* Ww = (const float*)d_in[2];
    const float* Wb = (const float*)d_in[3];
    const float* a  = (const float*)d_in[4];
    float* out = (float*)d_out;

    detect_kernel<<<1, 256>>>(ei);
    init_kernel<<<(N_NODES * HEADS + 255) / 256, 256>>>();

    dim3 ggrid(F_OUT / 128, (N_NODES + 127) / 128);
    gemm_kernel<<<ggrid, 256>>>(x, Ww, Wb, a);

    deg_kernel<<<(N_EDGES + 255) / 256, 256>>>(ei);
    scan_kernel<<<1, 1024>>>();
    scatter_kernel<<<(N_EDGES + 255) / 256, 256>>>();

    agg_kernel<<<(N_NODES * 32 + 255) / 256, 256>>>(out);
}

// round 6
// speedup vs baseline: 1.0791x; 1.0791x over previous
#include <cuda_runtime.h>
#include <cuda_bf16.h>
#include <math.h>

#define N_NODES 50000
#define IN_DIM  256
#define OUT_DIM 128
#define HEADS   2
#define F_OUT   256
#define N_EDGES 800000

/* ---------------- scratch ---------------- */
__device__ float g_Wh[(size_t)N_NODES * F_OUT];
__device__ float g_s[N_NODES * HEADS];
__device__ float g_t[N_NODES * HEADS];
__device__ int   g_deg[N_NODES];
__device__ int   g_row[N_NODES + 1];
__device__ int   g_cursor[N_NODES];
__device__ int   g_csr_dst[N_EDGES];
__device__ int   g_esrc[N_EDGES];
__device__ int   g_edst[N_EDGES];
__device__ int   g_is64;

/* ---------------- detect int32 vs int64 ---------------- */
__global__ void detect_kernel(const int* ei) {
    int v = ei[2 * threadIdx.x + 1];
    int any = __syncthreads_or(v != 0);
    if (threadIdx.x == 0) g_is64 = !any;
}

/* ---------------- init s/t (GEMM path) ---------------- */
__global__ void init_st_kernel() {
    int i = blockIdx.x * blockDim.x + threadIdx.x;
    if (i < N_NODES * HEADS) { g_s[i] = 0.0f; g_t[i] = 0.0f; }
}

/* ---------------- init deg (CSR path) ---------------- */
__global__ void init_deg_kernel() {
    int i = blockIdx.x * blockDim.x + threadIdx.x;
    if (i < N_NODES) g_deg[i] = 0;
}

/* ---------------- 3xBF16 split-GEMM (BM=128, BN=64), fused s/t ------ */
__device__ __forceinline__ void mma_bf16(float c[4], unsigned a0, unsigned a1,
                                         unsigned a2, unsigned a3,
                                         unsigned b0, unsigned b1) {
    asm volatile(
        "mma.sync.aligned.m16n8k16.row.col.f32.bf16.bf16.f32 "
        "{%0,%1,%2,%3},{%4,%5,%6,%7},{%8,%9},{%0,%1,%2,%3};"
        : "+f"(c[0]), "+f"(c[1]), "+f"(c[2]), "+f"(c[3])
        : "r"(a0), "r"(a1), "r"(a2), "r"(a3), "r"(b0), "r"(b1));
}

__device__ __forceinline__ void split2(float x, float y, unsigned& hi, unsigned& lo) {
    __nv_bfloat162 h = __floats2bfloat162_rn(x, y);
    float rx = x - __bfloat162float(h.x);
    float ry = y - __bfloat162float(h.y);
    __nv_bfloat162 l = __floats2bfloat162_rn(rx, ry);
    hi = *(unsigned*)&h;
    lo = *(unsigned*)&l;
}

__global__ void __launch_bounds__(256) gemm_kernel(const float* __restrict__ A,
                                                   const float* __restrict__ W,
                                                   const float* __restrict__ bias,
                                                   const float* __restrict__ a_vec) {
    __shared__ unsigned Ah[16][136];
    __shared__ unsigned Al[16][136];
    __shared__ unsigned Bh[16][72];
    __shared__ unsigned Bl[16][72];

    const int bm = blockIdx.y * 128;
    const int bn = blockIdx.x * 64;
    const int tid  = threadIdx.x;
    const int lane = tid & 31;
    const int wid  = tid >> 5;
    const int warp_m = wid >> 1;
    const int warp_n = wid & 1;
    const int g  = lane >> 2;
    const int tc = lane & 3;
    const int head = (bn >= 128) ? 1 : 0;

    float c[2][4][4];
    #pragma unroll
    for (int mi = 0; mi < 2; mi++)
        #pragma unroll
        for (int ni = 0; ni < 4; ni++)
            #pragma unroll
            for (int r = 0; r < 4; r++) c[mi][ni][r] = 0.0f;

    for (int k0 = 0; k0 < IN_DIM; k0 += 32) {
        #pragma unroll
        for (int p = 0; p < 4; p++) {
            int row = p * 32 + (tid >> 3);
            int kq  = (tid & 7) * 4;
            int kp  = kq >> 1;
            int gr  = bm + row;
            float4 v = make_float4(0.f, 0.f, 0.f, 0.f);
            if (gr < N_NODES)
                v = *(const float4*)&A[(size_t)gr * IN_DIM + k0 + kq];
            unsigned h0, l0, h1, l1;
            split2(v.x, v.y, h0, l0);
            split2(v.z, v.w, h1, l1);
            Ah[kp][row]     = h0;  Al[kp][row]     = l0;
            Ah[kp + 1][row] = h1;  Al[kp + 1][row] = l1;
        }
        {
            int kp = tid >> 4;
            int n4 = (tid & 15) * 4;
            const float* w0 = &W[(size_t)(k0 + 2 * kp) * F_OUT + bn + n4];
            float4 v0 = *(const float4*)w0;
            float4 v1 = *(const float4*)(w0 + F_OUT);
            unsigned h, l;
            split2(v0.x, v1.x, h, l); Bh[kp][n4 + 0] = h; Bl[kp][n4 + 0] = l;
            split2(v0.y, v1.y, h, l); Bh[kp][n4 + 1] = h; Bl[kp][n4 + 1] = l;
            split2(v0.z, v1.z, h, l); Bh[kp][n4 + 2] = h; Bl[kp][n4 + 2] = l;
            split2(v0.w, v1.w, h, l); Bh[kp][n4 + 3] = h; Bl[kp][n4 + 3] = l;
        }
        __syncthreads();

        #pragma unroll
        for (int kk = 0; kk < 2; kk++) {
            unsigned ah[2][4], al[2][4], bh[4][2], bl[4][2];
            #pragma unroll
            for (int mi = 0; mi < 2; mi++) {
                int rb = warp_m * 32 + mi * 16;
                int kp = kk * 8 + tc;
                ah[mi][0] = Ah[kp][rb + g];         al[mi][0] = Al[kp][rb + g];
                ah[mi][1] = Ah[kp][rb + g + 8];     al[mi][1] = Al[kp][rb + g + 8];
                ah[mi][2] = Ah[kp + 4][rb + g];     al[mi][2] = Al[kp + 4][rb + g];
                ah[mi][3] = Ah[kp + 4][rb + g + 8]; al[mi][3] = Al[kp + 4][rb + g + 8];
            }
            #pragma unroll
            for (int ni = 0; ni < 4; ni++) {
                int n = warp_n * 32 + ni * 8 + g;
                int kp = kk * 8 + tc;
                bh[ni][0] = Bh[kp][n];     bl[ni][0] = Bl[kp][n];
                bh[ni][1] = Bh[kp + 4][n]; bl[ni][1] = Bl[kp + 4][n];
            }
            #pragma unroll
            for (int mi = 0; mi < 2; mi++)
                #pragma unroll
                for (int ni = 0; ni < 4; ni++) {
                    mma_bf16(c[mi][ni], ah[mi][0], ah[mi][1], ah[mi][2], ah[mi][3],
                             bl[ni][0], bl[ni][1]);
                    mma_bf16(c[mi][ni], al[mi][0], al[mi][1], al[mi][2], al[mi][3],
                             bh[ni][0], bh[ni][1]);
                    mma_bf16(c[mi][ni], ah[mi][0], ah[mi][1], ah[mi][2], ah[mi][3],
                             bh[ni][0], bh[ni][1]);
                }
        }
        __syncthreads();
    }

    #pragma unroll
    for (int mi = 0; mi < 2; mi++) {
        int r0 = bm + warp_m * 32 + mi * 16 + g;
        int r1 = r0 + 8;
        float ps0 = 0.f, pt0 = 0.f, ps1 = 0.f, pt1 = 0.f;
        #pragma unroll
        for (int ni = 0; ni < 4; ni++) {
            int cb = bn + warp_n * 32 + ni * 8 + tc * 2;
            int dloc = cb - head * OUT_DIM;
            float b0 = bias[cb], b1 = bias[cb + 1];
            float as0 = a_vec[dloc],           as1 = a_vec[dloc + 1];
            float ad0 = a_vec[OUT_DIM + dloc], ad1 = a_vec[OUT_DIM + dloc + 1];
            float v00 = c[mi][ni][0] + b0, v01 = c[mi][ni][1] + b1;
            float v10 = c[mi][ni][2] + b0, v11 = c[mi][ni][3] + b1;
            if (r0 < N_NODES) {
                g_Wh[(size_t)r0 * F_OUT + cb]     = v00;
                g_Wh[(size_t)r0 * F_OUT + cb + 1] = v01;
            }
            if (r1 < N_NODES) {
                g_Wh[(size_t)r1 * F_OUT + cb]     = v10;
                g_Wh[(size_t)r1 * F_OUT + cb + 1] = v11;
            }
            ps0 = fmaf(v00, as0, fmaf(v01, as1, ps0));
            pt0 = fmaf(v00, ad0, fmaf(v01, ad1, pt0));
            ps1 = fmaf(v10, as0, fmaf(v11, as1, ps1));
            pt1 = fmaf(v10, ad0, fmaf(v11, ad1, pt1));
        }
        #pragma unroll
        for (int o = 2; o > 0; o >>= 1) {
            ps0 += __shfl_down_sync(0xffffffffu, ps0, o);
            pt0 += __shfl_down_sync(0xffffffffu, pt0, o);
            ps1 += __shfl_down_sync(0xffffffffu, ps1, o);
            pt1 += __shfl_down_sync(0xffffffffu, pt1, o);
        }
        if (tc == 0) {
            if (r0 < N_NODES) {
                atomicAdd(&g_s[2 * r0 + head], ps0);
                atomicAdd(&g_t[2 * r0 + head], pt0);
            }
            if (r1 < N_NODES) {
                atomicAdd(&g_s[2 * r1 + head], ps1);
                atomicAdd(&g_t[2 * r1 + head], pt1);
            }
        }
    }
}

/* ---------------- degree histogram + edge decode ---------------- */
__global__ void deg_kernel(const int* __restrict__ ei) {
    int i = blockIdx.x * blockDim.x + threadIdx.x;
    if (i >= N_EDGES) return;
    int src, dst;
    if (g_is64) { src = ei[2 * i]; dst = ei[2 * (N_EDGES + i)]; }
    else        { src = ei[i];     dst = ei[N_EDGES + i]; }
    g_esrc[i] = src;
    g_edst[i] = dst;
    atomicAdd(&g_deg[src], 1);
}

/* ---------------- single-block exclusive scan ---------------- */
__global__ void scan_kernel() {
    const int tid = threadIdx.x, lane = tid & 31, wid = tid >> 5;
    __shared__ int wsum[32];
    __shared__ int s_carry;
    if (tid == 0) s_carry = 0;
    __syncthreads();
    for (int base = 0; base < N_NODES; base += 8192) {
        int i0 = base + tid * 8;
        int v[8], pref[8];
        int run = 0;
        #pragma unroll
        for (int j = 0; j < 8; j++) {
            v[j] = (i0 + j < N_NODES) ? g_deg[i0 + j] : 0;
            pref[j] = run;
            run += v[j];
        }
        int x = run;
        #pragma unroll
        for (int o = 1; o < 32; o <<= 1) {
            int y = __shfl_up_sync(0xffffffffu, x, o);
            if (lane >= o) x += y;
        }
        if (lane == 31) wsum[wid] = x;
        __syncthreads();
        if (wid == 0) {
            int w = wsum[lane];
            #pragma unroll
            for (int o = 1; o < 32; o <<= 1) {
                int y = __shfl_up_sync(0xffffffffu, w, o);
                if (lane >= o) w += y;
            }
            wsum[lane] = w;
        }
        __syncthreads();
        int off = s_carry + ((wid == 0) ? 0 : wsum[wid - 1]) + (x - run);
        #pragma unroll
        for (int j = 0; j < 8; j++) {
            int i = i0 + j;
            if (i < N_NODES) { g_row[i] = off + pref[j]; g_cursor[i] = off + pref[j]; }
        }
        __syncthreads();
        if (tid == 0) s_carry += wsum[31];
        __syncthreads();
    }
    if (tid == 0) g_row[N_NODES] = s_carry;
}

/* ---------------- scatter into CSR ---------------- */
__global__ void scatter_kernel() {
    int i = blockIdx.x * blockDim.x + threadIdx.x;
    if (i >= N_EDGES) return;
    int src = g_esrc[i];
    int p = atomicAdd(&g_cursor[src], 1);
    g_csr_dst[p] = g_edst[i];
}

/* ---------------- fused softmax+agg (warp per node, unroll 2) ------ */
__global__ void __launch_bounds__(256) agg_kernel(float* __restrict__ out) {
    int n = (blockIdx.x * blockDim.x + threadIdx.x) >> 5;
    int lane = threadIdx.x & 31;
    if (n >= N_NODES) return;
    int start = g_row[n], end = g_row[n + 1];
    float* o = out + (size_t)n * F_OUT + lane * 8;
    const float* whn = g_Wh + (size_t)n * F_OUT + lane * 8;

    if (start == end) {
        *(float4*)o       = *(const float4*)whn;
        *(float4*)(o + 4) = *(const float4*)(whn + 4);
        return;
    }

    int head = lane >> 4;
    float s_h = g_s[2 * n + head];
    float4 acc0 = make_float4(0.f, 0.f, 0.f, 0.f);
    float4 acc1 = make_float4(0.f, 0.f, 0.f, 0.f);
    float den = 0.0f;

    int i = start;
    for (; i + 1 < end; i += 2) {
        int d0 = g_csr_dst[i];
        int d1 = g_csr_dst[i + 1];
        float t0 = g_t[2 * d0 + head];
        float t1 = g_t[2 * d1 + head];
        const float4* w0 = (const float4*)(g_Wh + (size_t)d0 * F_OUT + lane * 8);
        const float4* w1 = (const float4*)(g_Wh + (size_t)d1 * F_OUT + lane * 8);
        float4 v00 = w0[0], v01 = w0[1];
        float4 v10 = w1[0], v11 = w1[1];
        float e0 = s_h + t0; e0 = e0 > 0.f ? e0 : 0.2f * e0;
        float e1 = s_h + t1; e1 = e1 > 0.f ? e1 : 0.2f * e1;
        float ex0 = expf(e0);
        float ex1 = expf(e1);
        den += ex0 + ex1;
        acc0.x = fmaf(ex0, v00.x, acc0.x); acc0.y = fmaf(ex0, v00.y, acc0.y);
        acc0.z = fmaf(ex0, v00.z, acc0.z); acc0.w = fmaf(ex0, v00.w, acc0.w);
        acc1.x = fmaf(ex0, v01.x, acc1.x); acc1.y = fmaf(ex0, v01.y, acc1.y);
        acc1.z = fmaf(ex0, v01.z, acc1.z); acc1.w = fmaf(ex0, v01.w, acc1.w);
        acc0.x = fmaf(ex1, v10.x, acc0.x); acc0.y = fmaf(ex1, v10.y, acc0.y);
        acc0.z = fmaf(ex1, v10.z, acc0.z); acc0.w = fmaf(ex1, v10.w, acc0.w);
        acc1.x = fmaf(ex1, v11.x, acc1.x); acc1.y = fmaf(ex1, v11.y, acc1.y);
        acc1.z = fmaf(ex1, v11.z, acc1.z); acc1.w = fmaf(ex1, v11.w, acc1.w);
    }
    if (i < end) {
        int d = g_csr_dst[i];
        float t = g_t[2 * d + head];
        const float4* w = (const float4*)(g_Wh + (size_t)d * F_OUT + lane * 8);
        float4 v0 = w[0], v1 = w[1];
        float e = s_h + t; e = e > 0.f ? e : 0.2f * e;
        float ex = expf(e);
        den += ex;
        acc0.x = fmaf(ex, v0.x, acc0.x); acc0.y = fmaf(ex, v0.y, acc0.y);
        acc0.z = fmaf(ex, v0.z, acc0.z); acc0.w = fmaf(ex, v0.w, acc0.w);
        acc1.x = fmaf(ex, v1.x, acc1.x); acc1.y = fmaf(ex, v1.y, acc1.y);
        acc1.z = fmaf(ex, v1.z, acc1.z); acc1.w = fmaf(ex, v1.w, acc1.w);
    }
    float inv = 1.0f / den;
    acc0.x *= inv; acc0.y *= inv; acc0.z *= inv; acc0.w *= inv;
    acc1.x *= inv; acc1.y *= inv; acc1.z *= inv; acc1.w *= inv;
    *(float4*)o       = acc0;
    *(float4*)(o + 4) = acc1;
}

/* ---------------- launch: fork-join (GEMM || CSR build) ---------------- */
extern "C" void kernel_launch(void* const* d_in, const int* in_sizes, int n_in,
                              void* d_out, int out_size) {
    const float* x  = (const float*)d_in[0];
    const int*   ei = (const int*)d_in[1];
    const float* Ww = (const float*)d_in[2];
    const float* Wb = (const float*)d_in[3];
    const float* a  = (const float*)d_in[4];
    float* out = (float*)d_out;

    cudaStream_t side;
    cudaEvent_t ev_fork, ev_join;
    cudaStreamCreateWithFlags(&side, cudaStreamNonBlocking);
    cudaEventCreateWithFlags(&ev_fork, cudaEventDisableTiming);
    cudaEventCreateWithFlags(&ev_join, cudaEventDisableTiming);

    /* fork point: nothing launched yet on main; record marker */
    cudaEventRecord(ev_fork, 0);
    cudaStreamWaitEvent(side, ev_fork, 0);

    /* ---- side stream: CSR build path (depends only on edge_index) ---- */
    detect_kernel<<<1, 256, 0, side>>>(ei);
    init_deg_kernel<<<(N_NODES + 255) / 256, 256, 0, side>>>();
    deg_kernel<<<(N_EDGES + 255) / 256, 256, 0, side>>>(ei);
    scan_kernel<<<1, 1024, 0, side>>>();
    scatter_kernel<<<(N_EDGES + 255) / 256, 256, 0, side>>>();
    cudaEventRecord(ev_join, side);

    /* ---- main stream: GEMM path (depends only on x, W) ---- */
    init_st_kernel<<<(N_NODES * HEADS + 255) / 256, 256>>>();
    dim3 ggrid(F_OUT / 64, (N_NODES + 127) / 128);
    gemm_kernel<<<ggrid, 256>>>(x, Ww, Wb, a);

    /* ---- join, then aggregate ---- */
    cudaStreamWaitEvent(0, ev_join, 0);
    agg_kernel<<<(N_NODES * 32 + 255) / 256, 256>>>(out);
}

// round 7
// speedup vs baseline: 1.5123x; 1.4015x over previous
#include <cuda_runtime.h>
#include <cuda_bf16.h>
#include <cuda_fp16.h>
#include <math.h>

#define N_NODES 50000
#define IN_DIM  256
#define OUT_DIM 128
#define HEADS   2
#define F_OUT   256
#define N_EDGES 800000

#define SCAN_NB    49
#define SCAN_CHUNK 1024   /* 256 threads * 4 items */

/* ---------------- scratch ---------------- */
__device__ float   g_Wh[(size_t)N_NODES * F_OUT];
__device__ __half2 g_Whh[(size_t)N_NODES * (F_OUT / 2)];   /* fp16 mirror for gather */
__device__ float   g_s[N_NODES * HEADS];
__device__ float   g_t[N_NODES * HEADS];
__device__ int     g_deg[N_NODES];
__device__ int     g_row[N_NODES + 1];
__device__ int     g_cursor[N_NODES];
__device__ int     g_csr_dst[N_EDGES];
__device__ int     g_esrc[N_EDGES];
__device__ int     g_edst[N_EDGES];
__device__ int     g_bsum[SCAN_NB];
__device__ int     g_boff[SCAN_NB];
__device__ int     g_is64;

/* ---------------- detect int32 vs int64 ---------------- */
__global__ void detect_kernel(const int* ei) {
    int v = ei[2 * threadIdx.x + 1];
    int any = __syncthreads_or(v != 0);
    if (threadIdx.x == 0) g_is64 = !any;
}

/* ---------------- init s/t (GEMM path) ---------------- */
__global__ void init_st_kernel() {
    int i = blockIdx.x * blockDim.x + threadIdx.x;
    if (i < N_NODES * HEADS) { g_s[i] = 0.0f; g_t[i] = 0.0f; }
}

/* ---------------- init deg (CSR path) ---------------- */
__global__ void init_deg_kernel() {
    int i = blockIdx.x * blockDim.x + threadIdx.x;
    if (i < N_NODES) g_deg[i] = 0;
}

/* ---------------- 3xBF16 split-GEMM (BM=128, BN=64), fused s/t ------ */
__device__ __forceinline__ void mma_bf16(float c[4], unsigned a0, unsigned a1,
                                         unsigned a2, unsigned a3,
                                         unsigned b0, unsigned b1) {
    asm volatile(
        "mma.sync.aligned.m16n8k16.row.col.f32.bf16.bf16.f32 "
        "{%0,%1,%2,%3},{%4,%5,%6,%7},{%8,%9},{%0,%1,%2,%3};"
        : "+f"(c[0]), "+f"(c[1]), "+f"(c[2]), "+f"(c[3])
        : "r"(a0), "r"(a1), "r"(a2), "r"(a3), "r"(b0), "r"(b1));
}

__device__ __forceinline__ void split2(float x, float y, unsigned& hi, unsigned& lo) {
    __nv_bfloat162 h = __floats2bfloat162_rn(x, y);
    float rx = x - __bfloat162float(h.x);
    float ry = y - __bfloat162float(h.y);
    __nv_bfloat162 l = __floats2bfloat162_rn(rx, ry);
    hi = *(unsigned*)&h;
    lo = *(unsigned*)&l;
}

__global__ void __launch_bounds__(256) gemm_kernel(const float* __restrict__ A,
                                                   const float* __restrict__ W,
                                                   const float* __restrict__ bias,
                                                   const float* __restrict__ a_vec) {
    __shared__ unsigned Ah[16][136];
    __shared__ unsigned Al[16][136];
    __shared__ unsigned Bh[16][72];
    __shared__ unsigned Bl[16][72];

    const int bm = blockIdx.y * 128;
    const int bn = blockIdx.x * 64;
    const int tid  = threadIdx.x;
    const int lane = tid & 31;
    const int wid  = tid >> 5;
    const int warp_m = wid >> 1;
    const int warp_n = wid & 1;
    const int g  = lane >> 2;
    const int tc = lane & 3;
    const int head = (bn >= 128) ? 1 : 0;

    float c[2][4][4];
    #pragma unroll
    for (int mi = 0; mi < 2; mi++)
        #pragma unroll
        for (int ni = 0; ni < 4; ni++)
            #pragma unroll
            for (int r = 0; r < 4; r++) c[mi][ni][r] = 0.0f;

    for (int k0 = 0; k0 < IN_DIM; k0 += 32) {
        #pragma unroll
        for (int p = 0; p < 4; p++) {
            int row = p * 32 + (tid >> 3);
            int kq  = (tid & 7) * 4;
            int kp  = kq >> 1;
            int gr  = bm + row;
            float4 v = make_float4(0.f, 0.f, 0.f, 0.f);
            if (gr < N_NODES)
                v = *(const float4*)&A[(size_t)gr * IN_DIM + k0 + kq];
            unsigned h0, l0, h1, l1;
            split2(v.x, v.y, h0, l0);
            split2(v.z, v.w, h1, l1);
            Ah[kp][row]     = h0;  Al[kp][row]     = l0;
            Ah[kp + 1][row] = h1;  Al[kp + 1][row] = l1;
        }
        {
            int kp = tid >> 4;
            int n4 = (tid & 15) * 4;
            const float* w0 = &W[(size_t)(k0 + 2 * kp) * F_OUT + bn + n4];
            float4 v0 = *(const float4*)w0;
            float4 v1 = *(const float4*)(w0 + F_OUT);
            unsigned h, l;
            split2(v0.x, v1.x, h, l); Bh[kp][n4 + 0] = h; Bl[kp][n4 + 0] = l;
            split2(v0.y, v1.y, h, l); Bh[kp][n4 + 1] = h; Bl[kp][n4 + 1] = l;
            split2(v0.z, v1.z, h, l); Bh[kp][n4 + 2] = h; Bl[kp][n4 + 2] = l;
            split2(v0.w, v1.w, h, l); Bh[kp][n4 + 3] = h; Bl[kp][n4 + 3] = l;
        }
        __syncthreads();

        #pragma unroll
        for (int kk = 0; kk < 2; kk++) {
            unsigned ah[2][4], al[2][4], bh[4][2], bl[4][2];
            #pragma unroll
            for (int mi = 0; mi < 2; mi++) {
                int rb = warp_m * 32 + mi * 16;
                int kp = kk * 8 + tc;
                ah[mi][0] = Ah[kp][rb + g];         al[mi][0] = Al[kp][rb + g];
                ah[mi][1] = Ah[kp][rb + g + 8];     al[mi][1] = Al[kp][rb + g + 8];
                ah[mi][2] = Ah[kp + 4][rb + g];     al[mi][2] = Al[kp + 4][rb + g];
                ah[mi][3] = Ah[kp + 4][rb + g + 8]; al[mi][3] = Al[kp + 4][rb + g + 8];
            }
            #pragma unroll
            for (int ni = 0; ni < 4; ni++) {
                int n = warp_n * 32 + ni * 8 + g;
                int kp = kk * 8 + tc;
                bh[ni][0] = Bh[kp][n];     bl[ni][0] = Bl[kp][n];
                bh[ni][1] = Bh[kp + 4][n]; bl[ni][1] = Bl[kp + 4][n];
            }
            #pragma unroll
            for (int mi = 0; mi < 2; mi++)
                #pragma unroll
                for (int ni = 0; ni < 4; ni++) {
                    mma_bf16(c[mi][ni], ah[mi][0], ah[mi][1], ah[mi][2], ah[mi][3],
                             bl[ni][0], bl[ni][1]);
                    mma_bf16(c[mi][ni], al[mi][0], al[mi][1], al[mi][2], al[mi][3],
                             bh[ni][0], bh[ni][1]);
                    mma_bf16(c[mi][ni], ah[mi][0], ah[mi][1], ah[mi][2], ah[mi][3],
                             bh[ni][0], bh[ni][1]);
                }
        }
        __syncthreads();
    }

    #pragma unroll
    for (int mi = 0; mi < 2; mi++) {
        int r0 = bm + warp_m * 32 + mi * 16 + g;
        int r1 = r0 + 8;
        float ps0 = 0.f, pt0 = 0.f, ps1 = 0.f, pt1 = 0.f;
        #pragma unroll
        for (int ni = 0; ni < 4; ni++) {
            int cb = bn + warp_n * 32 + ni * 8 + tc * 2;
            int dloc = cb - head * OUT_DIM;
            float b0 = bias[cb], b1 = bias[cb + 1];
            float as0 = a_vec[dloc],           as1 = a_vec[dloc + 1];
            float ad0 = a_vec[OUT_DIM + dloc], ad1 = a_vec[OUT_DIM + dloc + 1];
            float v00 = c[mi][ni][0] + b0, v01 = c[mi][ni][1] + b1;
            float v10 = c[mi][ni][2] + b0, v11 = c[mi][ni][3] + b1;
            if (r0 < N_NODES) {
                g_Wh[(size_t)r0 * F_OUT + cb]     = v00;
                g_Wh[(size_t)r0 * F_OUT + cb + 1] = v01;
                g_Whh[(size_t)r0 * (F_OUT / 2) + (cb >> 1)] = __floats2half2_rn(v00, v01);
            }
            if (r1 < N_NODES) {
                g_Wh[(size_t)r1 * F_OUT + cb]     = v10;
                g_Wh[(size_t)r1 * F_OUT + cb + 1] = v11;
                g_Whh[(size_t)r1 * (F_OUT / 2) + (cb >> 1)] = __floats2half2_rn(v10, v11);
            }
            ps0 = fmaf(v00, as0, fmaf(v01, as1, ps0));
            pt0 = fmaf(v00, ad0, fmaf(v01, ad1, pt0));
            ps1 = fmaf(v10, as0, fmaf(v11, as1, ps1));
            pt1 = fmaf(v10, ad0, fmaf(v11, ad1, pt1));
        }
        #pragma unroll
        for (int o = 2; o > 0; o >>= 1) {
            ps0 += __shfl_down_sync(0xffffffffu, ps0, o);
            pt0 += __shfl_down_sync(0xffffffffu, pt0, o);
            ps1 += __shfl_down_sync(0xffffffffu, ps1, o);
            pt1 += __shfl_down_sync(0xffffffffu, pt1, o);
        }
        if (tc == 0) {
            if (r0 < N_NODES) {
                atomicAdd(&g_s[2 * r0 + head], ps0);
                atomicAdd(&g_t[2 * r0 + head], pt0);
            }
            if (r1 < N_NODES) {
                atomicAdd(&g_s[2 * r1 + head], ps1);
                atomicAdd(&g_t[2 * r1 + head], pt1);
            }
        }
    }
}

/* ---------------- degree histogram + edge decode ---------------- */
__global__ void deg_kernel(const int* __restrict__ ei) {
    int i = blockIdx.x * blockDim.x + threadIdx.x;
    if (i >= N_EDGES) return;
    int src, dst;
    if (g_is64) { src = ei[2 * i]; dst = ei[2 * (N_EDGES + i)]; }
    else        { src = ei[i];     dst = ei[N_EDGES + i]; }
    g_esrc[i] = src;
    g_edst[i] = dst;
    atomicAdd(&g_deg[src], 1);
}

/* ---------------- multi-block scan: phase A (block sums) ---------------- */
__global__ void __launch_bounds__(256) scanA_kernel() {
    const int tid = threadIdx.x, lane = tid & 31, wid = tid >> 5;
    __shared__ int wsum[8];
    int i0 = blockIdx.x * SCAN_CHUNK + tid * 4;
    int s = 0;
    #pragma unroll
    for (int j = 0; j < 4; j++) {
        int i = i0 + j;
        s += (i < N_NODES) ? g_deg[i] : 0;
    }
    #pragma unroll
    for (int o = 16; o > 0; o >>= 1) s += __shfl_down_sync(0xffffffffu, s, o);
    if (lane == 0) wsum[wid] = s;
    __syncthreads();
    if (tid == 0) {
        int t = 0;
        #pragma unroll
        for (int w = 0; w < 8; w++) t += wsum[w];
        g_bsum[blockIdx.x] = t;
    }
}

/* ---------------- phase B: scan 49 block sums ---------------- */
__global__ void scanB_kernel() {
    __shared__ int sh[SCAN_NB];
    int tid = threadIdx.x;
    if (tid < SCAN_NB) sh[tid] = g_bsum[tid];
    __syncthreads();
    if (tid == 0) {
        int run = 0;
        for (int b = 0; b < SCAN_NB; b++) {
            g_boff[b] = run;
            run += sh[b];
        }
        g_row[N_NODES] = run;
    }
}

/* ---------------- phase C: per-block exclusive scan + offset ---------- */
__global__ void __launch_bounds__(256) scanC_kernel() {
    const int tid = threadIdx.x, lane = tid & 31, wid = tid >> 5;
    __shared__ int wsum[8];
    int i0 = blockIdx.x * SCAN_CHUNK + tid * 4;
    int v[4], pref[4];
    int run = 0;
    #pragma unroll
    for (int j = 0; j < 4; j++) {
        v[j] = (i0 + j < N_NODES) ? g_deg[i0 + j] : 0;
        pref[j] = run;
        run += v[j];
    }
    int x = run;
    #pragma unroll
    for (int o = 1; o < 32; o <<= 1) {
        int y = __shfl_up_sync(0xffffffffu, x, o);
        if (lane >= o) x += y;
    }
    if (lane == 31) wsum[wid] = x;
    __syncthreads();
    int warp_off = 0;
    #pragma unroll
    for (int w = 0; w < 8; w++)
        if (w < wid) warp_off += wsum[w];
    int base = g_boff[blockIdx.x] + warp_off + (x - run);
    #pragma unroll
    for (int j = 0; j < 4; j++) {
        int i = i0 + j;
        if (i < N_NODES) { g_row[i] = base + pref[j]; g_cursor[i] = base + pref[j]; }
    }
}

/* ---------------- scatter into CSR ---------------- */
__global__ void scatter_kernel() {
    int i = blockIdx.x * blockDim.x + threadIdx.x;
    if (i >= N_EDGES) return;
    int src = g_esrc[i];
    int p = atomicAdd(&g_cursor[src], 1);
    g_csr_dst[p] = g_edst[i];
}

/* ---------------- fused softmax+agg (warp per node, half2 gather) ------ */
__device__ __forceinline__ void acc_edge(float ex, float4 raw, float* acc) {
    float2 f0 = __half22float2(*(__half2*)&raw.x);
    float2 f1 = __half22float2(*(__half2*)&raw.y);
    float2 f2 = __half22float2(*(__half2*)&raw.z);
    float2 f3 = __half22float2(*(__half2*)&raw.w);
    acc[0] = fmaf(ex, f0.x, acc[0]); acc[1] = fmaf(ex, f0.y, acc[1]);
    acc[2] = fmaf(ex, f1.x, acc[2]); acc[3] = fmaf(ex, f1.y, acc[3]);
    acc[4] = fmaf(ex, f2.x, acc[4]); acc[5] = fmaf(ex, f2.y, acc[5]);
    acc[6] = fmaf(ex, f3.x, acc[6]); acc[7] = fmaf(ex, f3.y, acc[7]);
}

__global__ void __launch_bounds__(256) agg_kernel(float* __restrict__ out) {
    int n = (blockIdx.x * blockDim.x + threadIdx.x) >> 5;
    int lane = threadIdx.x & 31;
    if (n >= N_NODES) return;
    int start = g_row[n], end = g_row[n + 1];
    float* o = out + (size_t)n * F_OUT + lane * 8;

    if (start == end) {
        const float* whn = g_Wh + (size_t)n * F_OUT + lane * 8;
        *(float4*)o       = *(const float4*)whn;
        *(float4*)(o + 4) = *(const float4*)(whn + 4);
        return;
    }

    int head = lane >> 4;
    float s_h = g_s[2 * n + head];
    float acc[8] = {0.f, 0.f, 0.f, 0.f, 0.f, 0.f, 0.f, 0.f};
    float den = 0.0f;

    const float4* whh_base = (const float4*)g_Whh;   /* 4 half2 = 1 float4 per lane */
    /* node d's lane slice: index d*32 + lane  (128 half2 per node = 32 float4) */

    int i = start;
    for (; i + 3 < end; i += 4) {
        int d0 = g_csr_dst[i];
        int d1 = g_csr_dst[i + 1];
        int d2 = g_csr_dst[i + 2];
        int d3 = g_csr_dst[i + 3];
        float t0 = g_t[2 * d0 + head];
        float t1 = g_t[2 * d1 + head];
        float t2 = g_t[2 * d2 + head];
        float t3 = g_t[2 * d3 + head];
        float4 r0 = whh_base[(size_t)d0 * 32 + lane];
        float4 r1 = whh_base[(size_t)d1 * 32 + lane];
        float4 r2 = whh_base[(size_t)d2 * 32 + lane];
        float4 r3 = whh_base[(size_t)d3 * 32 + lane];
        float e0 = s_h + t0; e0 = e0 > 0.f ? e0 : 0.2f * e0;
        float e1 = s_h + t1; e1 = e1 > 0.f ? e1 : 0.2f * e1;
        float e2 = s_h + t2; e2 = e2 > 0.f ? e2 : 0.2f * e2;
        float e3 = s_h + t3; e3 = e3 > 0.f ? e3 : 0.2f * e3;
        float ex0 = expf(e0), ex1 = expf(e1), ex2 = expf(e2), ex3 = expf(e3);
        den += (ex0 + ex1) + (ex2 + ex3);
        acc_edge(ex0, r0, acc);
        acc_edge(ex1, r1, acc);
        acc_edge(ex2, r2, acc);
        acc_edge(ex3, r3, acc);
    }
    for (; i < end; i++) {
        int d = g_csr_dst[i];
        float t = g_t[2 * d + head];
        float4 r = whh_base[(size_t)d * 32 + lane];
        float e = s_h + t; e = e > 0.f ? e : 0.2f * e;
        float ex = expf(e);
        den += ex;
        acc_edge(ex, r, acc);
    }
    float inv = 1.0f / den;
    #pragma unroll
    for (int j = 0; j < 8; j++) acc[j] *= inv;
    *(float4*)o       = make_float4(acc[0], acc[1], acc[2], acc[3]);
    *(float4*)(o + 4) = make_float4(acc[4], acc[5], acc[6], acc[7]);
}

/* ---------------- launch: fork-join (GEMM || CSR build) ---------------- */
extern "C" void kernel_launch(void* const* d_in, const int* in_sizes, int n_in,
                              void* d_out, int out_size) {
    const float* x  = (const float*)d_in[0];
    const int*   ei = (const int*)d_in[1];
    const float* Ww = (const float*)d_in[2];
    const float* Wb = (const float*)d_in[3];
    const float* a  = (const float*)d_in[4];
    float* out = (float*)d_out;

    cudaStream_t side;
    cudaEvent_t ev_fork, ev_join;
    cudaStreamCreateWithFlags(&side, cudaStreamNonBlocking);
    cudaEventCreateWithFlags(&ev_fork, cudaEventDisableTiming);
    cudaEventCreateWithFlags(&ev_join, cudaEventDisableTiming);

    cudaEventRecord(ev_fork, 0);
    cudaStreamWaitEvent(side, ev_fork, 0);

    /* ---- side stream: CSR build ---- */
    detect_kernel<<<1, 256, 0, side>>>(ei);
    init_deg_kernel<<<(N_NODES + 255) / 256, 256, 0, side>>>();
    deg_kernel<<<(N_EDGES + 255) / 256, 256, 0, side>>>(ei);
    scanA_kernel<<<SCAN_NB, 256, 0, side>>>();
    scanB_kernel<<<1, 64, 0, side>>>();
    scanC_kernel<<<SCAN_NB, 256, 0, side>>>();
    scatter_kernel<<<(N_EDGES + 255) / 256, 256, 0, side>>>();
    cudaEventRecord(ev_join, side);

    /* ---- main stream: GEMM ---- */
    init_st_kernel<<<(N_NODES * HEADS + 255) / 256, 256>>>();
    dim3 ggrid(F_OUT / 64, (N_NODES + 127) / 128);
    gemm_kernel<<<ggrid, 256>>>(x, Ww, Wb, a);

    /* ---- join, then aggregate ---- */
    cudaStreamWaitEvent(0, ev_join, 0);
    agg_kernel<<<(N_NODES * 32 + 255) / 256, 256>>>(out);
}